// round 4
// baseline (speedup 1.0000x reference)
#include <cuda_runtime.h>
#include <cstdint>
#include <cstddef>

#define Bz 32
#define Dd 1024
#define Ff 512
#define Hh 16
#define Oo 4
#define FC 4096

// Deterministic scratch (no device allocation allowed)
__device__ float g_logits[Oo * Bz * Hh * Ff];        // [o][b][h][f]  4 MB
__device__ float g_hcat_part[8 * Bz * FC];           // [chunk][b][o*1024+d]
__device__ float g_hcat[Bz * FC];                    // [b][o*1024+d]
__device__ float g_hidden_part[16 * Bz * FC];        // [kblk][b][j]

// ---------------------------------------------------------------------------
// Kernel A: logits[o,b,h,f] = (x[f,b,h,:] . q[o,h,:]) / 8, masked to -50
// Block = (b, 8-frame tile), 512 threads. q and x staged in padded smem:
//   q rows padded to 67 floats  -> bank (3*oh+s)%32, conflict-free over 32 lanes
//   x rows padded to 66 floats  -> bank (2*h+s)%32, conflict-free (o-pairs bcast)
// ---------------------------------------------------------------------------
__global__ void k_logits(const float* __restrict__ x, const int* __restrict__ nfp,
                         const float* __restrict__ q) {
    extern __shared__ float sm[];
    float* qs = sm;                 // 64 * 67
    float* xs = sm + 64 * 67;       // 8 * (16*66) = 8 * 1056
    int b  = blockIdx.x;
    int f0 = blockIdx.y * 8;
    int t  = threadIdx.x;
    int nf = nfp[b];

    for (int i = t; i < 64 * 64; i += 512)
        qs[(i >> 6) * 67 + (i & 63)] = q[i];

    // float2 staging: pad-66 rows keep even-j elements 8B-aligned
    for (int i = t; i < 8 * 512; i += 512) {
        int ff = i >> 9, j2 = i & 511;
        if (f0 + ff < nf) {
            int j = j2 * 2;
            float2 v = *(const float2*)&x[((size_t)(f0 + ff) * Bz + b) * Dd + j];
            *(float2*)&xs[ff * 1056 + (j >> 6) * 66 + (j & 63)] = v;
        }
    }
    __syncthreads();

    int fl = t >> 6;
    int oh = t & 63;
    int o = oh >> 4, h = oh & 15;
    int f = f0 + fl;

    float acc;
    if (f >= nf) {
        acc = -50.0f;
    } else {
        const float* xp = xs + fl * 1056 + h * 66;
        const float* qp = qs + oh * 67;
        float a = 0.f;
#pragma unroll
        for (int s = 0; s < 64; s++) a = fmaf(xp[s], qp[s], a);
        acc = a * 0.125f;
    }
    g_logits[((size_t)(o * Bz + b) * Hh + h) * Ff + f] = acc;
}

// ---------------------------------------------------------------------------
// Kernel B: softmax over f (per (o,b,h) column, incl. the -50 masked entries),
// writes attn in reference layout [o][f][b][h].
// ---------------------------------------------------------------------------
__global__ void k_softmax(float* __restrict__ attn) {
    int ob = blockIdx.x;
    int o = ob >> 5, b = ob & 31;
    int t = threadIdx.x;           // 256
    int w = t >> 5, lane = t & 31;

    __shared__ float ls[Hh * Ff];  // 32 KB
    __shared__ float si[Hh];

    const float* src = g_logits + (size_t)(o * Bz + b) * Hh * Ff;
    for (int i = t; i < Hh * Ff; i += 256) ls[i] = src[i];
    __syncthreads();

    for (int hh = w; hh < Hh; hh += 8) {
        float* lp = ls + hh * Ff;
        float m = -1e30f;
        for (int k = lane; k < Ff; k += 32) m = fmaxf(m, lp[k]);
#pragma unroll
        for (int off = 16; off; off >>= 1)
            m = fmaxf(m, __shfl_xor_sync(0xffffffffu, m, off));
        float s = 0.f;
        for (int k = lane; k < Ff; k += 32) {
            float e = __expf(lp[k] - m);
            lp[k] = e;
            s += e;
        }
#pragma unroll
        for (int off = 16; off; off >>= 1)
            s += __shfl_xor_sync(0xffffffffu, s, off);
        if (lane == 0) si[hh] = 1.0f / s;
    }
    __syncthreads();

    float* dst = attn + (size_t)o * Ff * Bz * Hh + b * Hh;
    for (int i = t; i < Hh * Ff; i += 256) {
        int f = i >> 4, hh = i & 15;
        dst[(size_t)f * (Bz * Hh) + hh] = ls[hh * Ff + f] * si[hh];
    }
}

// ---------------------------------------------------------------------------
// Kernel C: partial weighted sums over 64-frame chunks (no atomics —
// deterministic). Fast path for full chunks (unroll-4 -> MLP=4).
// ---------------------------------------------------------------------------
__global__ void k_wsum(const float* __restrict__ x, const int* __restrict__ nfp,
                       const float* __restrict__ attn) {
    int b = blockIdx.x;
    int c = blockIdx.y;
    int f0 = c * 64;
    int nf = nfp[b];
    int d = threadIdx.x;
    int h = d >> 6;

    __shared__ float as[4 * 64 * 16];   // [o][fl][h] 16 KB
    float a0 = 0.f, a1 = 0.f, a2 = 0.f, a3 = 0.f;

    if (f0 < nf) {
        for (int i = d; i < 4096; i += 1024) {
            int o = i >> 10, r = i & 1023;   // r = fl*16 + h
            as[i] = attn[(size_t)o * (Ff * Bz * Hh) +
                         (size_t)(f0 + (r >> 4)) * (Bz * Hh) + b * Hh + (r & 15)];
        }
        __syncthreads();
        int fe = min(64, nf - f0);
        const float* xp = x + ((size_t)f0 * Bz + b) * Dd + d;
        if (fe == 64) {
#pragma unroll 4
            for (int fl = 0; fl < 64; fl++) {
                float xv = xp[(size_t)fl * (Bz * Dd)];
                int ai = fl * 16 + h;
                a0 = fmaf(xv, as[ai],        a0);
                a1 = fmaf(xv, as[1024 + ai], a1);
                a2 = fmaf(xv, as[2048 + ai], a2);
                a3 = fmaf(xv, as[3072 + ai], a3);
            }
        } else {
            for (int fl = 0; fl < fe; fl++) {
                float xv = xp[(size_t)fl * (Bz * Dd)];
                int ai = fl * 16 + h;
                a0 = fmaf(xv, as[ai],        a0);
                a1 = fmaf(xv, as[1024 + ai], a1);
                a2 = fmaf(xv, as[2048 + ai], a2);
                a3 = fmaf(xv, as[3072 + ai], a3);
            }
        }
    }
    float* p = g_hcat_part + ((size_t)c * Bz + b) * FC + d;
    p[0] = a0; p[1024] = a1; p[2048] = a2; p[3072] = a3;
}

// Reduce the 8 chunk partials into hcat[b][o*1024+d]  (float4-wide)
__global__ void k_csum() {
    int i = (blockIdx.x * blockDim.x + threadIdx.x) * 4;   // Bz*FC/4 threads
    float4 s = make_float4(0.f, 0.f, 0.f, 0.f);
#pragma unroll
    for (int c = 0; c < 8; c++) {
        float4 v = *(const float4*)&g_hcat_part[(size_t)c * (Bz * FC) + i];
        s.x += v.x; s.y += v.y; s.z += v.z; s.w += v.w;
    }
    *(float4*)&g_hcat[i] = s;
}

// ---------------------------------------------------------------------------
// Kernel D: hidden_part[kb][b][j] = sum_{k in kb-range} hcat[b][k] * W1[k][j]
// Packed f32x2 FMA path: 16 b64 accumulators, hs rows read as ulonglong2
// (pairs of consecutive b), W1 element broadcast-packed into both halves.
// Per k: 1 LDG + 1 pack + 8 LDS.128 + 16 fma.f32x2 (was 32 FFMA).
// ---------------------------------------------------------------------------
__global__ void __launch_bounds__(128, 2) k_gemm1(const float* __restrict__ W1) {
    int t = threadIdx.x;                  // 128
    int j = blockIdx.x * 128 + t;
    int k0 = blockIdx.y * 256;

    __shared__ float hs[128 * 36];        // 18 KB, rows (144 B) 16B-aligned
    unsigned long long acc[16];
#pragma unroll
    for (int i = 0; i < 16; i++) acc[i] = 0ULL;   // (+0.f, +0.f)

    for (int kt = 0; kt < 2; kt++) {
        int kb = k0 + kt * 128;
        __syncthreads();
        for (int i = t; i < 32 * 128; i += 128) {
            int b = i >> 7, kl = i & 127;
            hs[kl * 36 + b] = g_hcat[(size_t)b * FC + kb + kl];
        }
        __syncthreads();
        const float* wp = W1 + (size_t)kb * FC + j;
#pragma unroll 4
        for (int kl = 0; kl < 128; kl++) {
            float w = wp[(size_t)kl * FC];
            unsigned long long w2;
            asm("mov.b64 %0, {%1, %1};" : "=l"(w2) : "r"(__float_as_uint(w)));
            const ulonglong2* hp = (const ulonglong2*)&hs[kl * 36];
#pragma unroll
            for (int q = 0; q < 8; q++) {
                ulonglong2 hv = hp[q];
                asm("fma.rn.f32x2 %0, %1, %2, %0;"
                    : "+l"(acc[2 * q])     : "l"(hv.x), "l"(w2));
                asm("fma.rn.f32x2 %0, %1, %2, %0;"
                    : "+l"(acc[2 * q + 1]) : "l"(hv.y), "l"(w2));
            }
        }
    }
    float* dst = g_hidden_part + (size_t)blockIdx.y * (Bz * FC) + j;
#pragma unroll
    for (int q = 0; q < 16; q++) {
        unsigned int lo, hi;
        asm("mov.b64 {%0, %1}, %2;" : "=r"(lo), "=r"(hi) : "l"(acc[q]));
        dst[(size_t)(2 * q) * FC]     = __uint_as_float(lo);
        dst[(size_t)(2 * q + 1) * FC] = __uint_as_float(hi);
    }
}

// ---------------------------------------------------------------------------
// Kernel E: out[b][n] = b2[n] + sum_j relu(sum_kb hidden_part + b1[j]) * W2[j][n]
// ---------------------------------------------------------------------------
__global__ void k_out(const float* __restrict__ b1, const float* __restrict__ W2,
                      const float* __restrict__ b2, float* __restrict__ out) {
    int b = blockIdx.x;
    int t = threadIdx.x;   // 512
    float a0 = 0.f, a1 = 0.f, a2 = 0.f, a3 = 0.f;

    for (int j = t; j < FC; j += 512) {
        float hv = b1[j];
#pragma unroll
        for (int kb = 0; kb < 16; kb++)
            hv += g_hidden_part[((size_t)kb * Bz + b) * FC + j];
        hv = fmaxf(hv, 0.f);
        float4 w = *(const float4*)(W2 + (size_t)j * 4);
        a0 = fmaf(hv, w.x, a0);
        a1 = fmaf(hv, w.y, a1);
        a2 = fmaf(hv, w.z, a2);
        a3 = fmaf(hv, w.w, a3);
    }
#pragma unroll
    for (int off = 16; off; off >>= 1) {
        a0 += __shfl_xor_sync(0xffffffffu, a0, off);
        a1 += __shfl_xor_sync(0xffffffffu, a1, off);
        a2 += __shfl_xor_sync(0xffffffffu, a2, off);
        a3 += __shfl_xor_sync(0xffffffffu, a3, off);
    }
    __shared__ float s[16][4];
    if ((t & 31) == 0) {
        int w = t >> 5;
        s[w][0] = a0; s[w][1] = a1; s[w][2] = a2; s[w][3] = a3;
    }
    __syncthreads();
    if (t < 4) {
        float r = 0.f;
#pragma unroll
        for (int w = 0; w < 16; w++) r += s[w][t];
        out[b * 4 + t] = r + b2[t];
    }
}

// ---------------------------------------------------------------------------
extern "C" void kernel_launch(void* const* d_in, const int* in_sizes, int n_in,
                              void* d_out, int out_size) {
    const float* x  = (const float*)d_in[0];
    const int*   nf = (const int*)  d_in[1];
    const float* q  = (const float*)d_in[2];
    const float* W1 = (const float*)d_in[3];
    const float* b1 = (const float*)d_in[4];
    const float* W2 = (const float*)d_in[5];
    const float* b2 = (const float*)d_in[6];

    float* out_p  = (float*)d_out;              // (B, 4) = 128 floats
    float* attn_p = out_p + Bz * Oo;            // (O, F, B, H) = 1,048,576 floats

    const int smemA = (64 * 67 + 8 * 1056) * 4; // 50944 B > 48 KB default
    cudaFuncSetAttribute(k_logits, cudaFuncAttributeMaxDynamicSharedMemorySize, smemA);

    dim3 gA(Bz, Ff / 8);
    k_logits<<<gA, 512, smemA>>>(x, nf, q);

    k_softmax<<<Oo * Bz, 256>>>(attn_p);

    dim3 gC(Bz, 8);
    k_wsum<<<gC, 1024>>>(x, nf, attn_p);

    k_csum<<<(Bz * FC) / (256 * 4), 256>>>();

    dim3 gD(FC / 128, 16);
    k_gemm1<<<gD, 128>>>(W1);

    k_out<<<Bz, 512>>>(b1, W2, b2, out_p);
}

// round 5
// speedup vs baseline: 1.2359x; 1.2359x over previous
#include <cuda_runtime.h>
#include <cstdint>
#include <cstddef>

#define Bz 32
#define Dd 1024
#define Ff 512
#define Hh 16
#define Oo 4
#define FC 4096

// Deterministic scratch (no device allocation allowed)
__device__ float g_logits[Oo * Bz * Hh * Ff];        // [o][b][h][f]  4 MB
__device__ float g_hcat_part[8 * Bz * FC];           // [chunk][b][o*1024+d]
__device__ float g_hcat[Bz * FC];                    // [b][o*1024+d]
__device__ float g_hidden_part[16 * Bz * FC];        // [kblk][b][j]
__device__ float g_dummy;

// Observability shim: shifts ncu's fixed capture slot onto k_wsum.
__global__ void k_dummy() { g_dummy = 1.0f; }

// ---------------------------------------------------------------------------
// Kernel A: logits[o,b,h,f] = (x[f,b,h,:] . q[o,h,:]) / 8, masked to -50
// Block = (b, 8-frame tile), 512 threads. q and x staged in padded smem:
//   q rows padded to 67 floats  -> bank (3*oh+s)%32, conflict-free over 32 lanes
//   x rows padded to 66 floats  -> bank (2*h+s)%32, conflict-free (o-pairs bcast)
// ---------------------------------------------------------------------------
__global__ void k_logits(const float* __restrict__ x, const int* __restrict__ nfp,
                         const float* __restrict__ q) {
    extern __shared__ float sm[];
    float* qs = sm;                 // 64 * 67
    float* xs = sm + 64 * 67;       // 8 * (16*66) = 8 * 1056
    int b  = blockIdx.x;
    int f0 = blockIdx.y * 8;
    int t  = threadIdx.x;
    int nf = nfp[b];

    for (int i = t; i < 64 * 64; i += 512)
        qs[(i >> 6) * 67 + (i & 63)] = q[i];

    // float2 staging: pad-66 rows keep even-j elements 8B-aligned
    for (int i = t; i < 8 * 512; i += 512) {
        int ff = i >> 9, j2 = i & 511;
        if (f0 + ff < nf) {
            int j = j2 * 2;
            float2 v = *(const float2*)&x[((size_t)(f0 + ff) * Bz + b) * Dd + j];
            *(float2*)&xs[ff * 1056 + (j >> 6) * 66 + (j & 63)] = v;
        }
    }
    __syncthreads();

    int fl = t >> 6;
    int oh = t & 63;
    int o = oh >> 4, h = oh & 15;
    int f = f0 + fl;

    float acc;
    if (f >= nf) {
        acc = -50.0f;
    } else {
        const float* xp = xs + fl * 1056 + h * 66;
        const float* qp = qs + oh * 67;
        float a = 0.f;
#pragma unroll
        for (int s = 0; s < 64; s++) a = fmaf(xp[s], qp[s], a);
        acc = a * 0.125f;
    }
    g_logits[((size_t)(o * Bz + b) * Hh + h) * Ff + f] = acc;
}

// ---------------------------------------------------------------------------
// Kernel B: softmax over f (per (o,b,h) column, incl. the -50 masked entries),
// writes attn in reference layout [o][f][b][h].
// ---------------------------------------------------------------------------
__global__ void k_softmax(float* __restrict__ attn) {
    int ob = blockIdx.x;
    int o = ob >> 5, b = ob & 31;
    int t = threadIdx.x;           // 256
    int w = t >> 5, lane = t & 31;

    __shared__ float ls[Hh * Ff];  // 32 KB
    __shared__ float si[Hh];

    const float* src = g_logits + (size_t)(o * Bz + b) * Hh * Ff;
    for (int i = t; i < Hh * Ff; i += 256) ls[i] = src[i];
    __syncthreads();

    for (int hh = w; hh < Hh; hh += 8) {
        float* lp = ls + hh * Ff;
        float m = -1e30f;
        for (int k = lane; k < Ff; k += 32) m = fmaxf(m, lp[k]);
#pragma unroll
        for (int off = 16; off; off >>= 1)
            m = fmaxf(m, __shfl_xor_sync(0xffffffffu, m, off));
        float s = 0.f;
        for (int k = lane; k < Ff; k += 32) {
            float e = __expf(lp[k] - m);
            lp[k] = e;
            s += e;
        }
#pragma unroll
        for (int off = 16; off; off >>= 1)
            s += __shfl_xor_sync(0xffffffffu, s, off);
        if (lane == 0) si[hh] = 1.0f / s;
    }
    __syncthreads();

    float* dst = attn + (size_t)o * Ff * Bz * Hh + b * Hh;
    for (int i = t; i < Hh * Ff; i += 256) {
        int f = i >> 4, hh = i & 15;
        dst[(size_t)f * (Bz * Hh) + hh] = ls[hh * Ff + f] * si[hh];
    }
}

// ---------------------------------------------------------------------------
// Kernel C: partial weighted sums over 64-frame chunks (no atomics —
// deterministic). Fast path for full chunks (unroll-4 -> MLP=4).
// ---------------------------------------------------------------------------
__global__ void k_wsum(const float* __restrict__ x, const int* __restrict__ nfp,
                       const float* __restrict__ attn) {
    int b = blockIdx.x;
    int c = blockIdx.y;
    int f0 = c * 64;
    int nf = nfp[b];
    int d = threadIdx.x;
    int h = d >> 6;

    __shared__ float as[4 * 64 * 16];   // [o][fl][h] 16 KB
    float a0 = 0.f, a1 = 0.f, a2 = 0.f, a3 = 0.f;

    if (f0 < nf) {
        for (int i = d; i < 4096; i += 1024) {
            int o = i >> 10, r = i & 1023;   // r = fl*16 + h
            as[i] = attn[(size_t)o * (Ff * Bz * Hh) +
                         (size_t)(f0 + (r >> 4)) * (Bz * Hh) + b * Hh + (r & 15)];
        }
        __syncthreads();
        int fe = min(64, nf - f0);
        const float* xp = x + ((size_t)f0 * Bz + b) * Dd + d;
        if (fe == 64) {
#pragma unroll 4
            for (int fl = 0; fl < 64; fl++) {
                float xv = xp[(size_t)fl * (Bz * Dd)];
                int ai = fl * 16 + h;
                a0 = fmaf(xv, as[ai],        a0);
                a1 = fmaf(xv, as[1024 + ai], a1);
                a2 = fmaf(xv, as[2048 + ai], a2);
                a3 = fmaf(xv, as[3072 + ai], a3);
            }
        } else {
            for (int fl = 0; fl < fe; fl++) {
                float xv = xp[(size_t)fl * (Bz * Dd)];
                int ai = fl * 16 + h;
                a0 = fmaf(xv, as[ai],        a0);
                a1 = fmaf(xv, as[1024 + ai], a1);
                a2 = fmaf(xv, as[2048 + ai], a2);
                a3 = fmaf(xv, as[3072 + ai], a3);
            }
        }
    }
    float* p = g_hcat_part + ((size_t)c * Bz + b) * FC + d;
    p[0] = a0; p[1024] = a1; p[2048] = a2; p[3072] = a3;
}

// Reduce the 8 chunk partials into hcat[b][o*1024+d]  (float4-wide)
__global__ void k_csum() {
    int i = (blockIdx.x * blockDim.x + threadIdx.x) * 4;   // Bz*FC/4 threads
    float4 s = make_float4(0.f, 0.f, 0.f, 0.f);
#pragma unroll
    for (int c = 0; c < 8; c++) {
        float4 v = *(const float4*)&g_hcat_part[(size_t)c * (Bz * FC) + i];
        s.x += v.x; s.y += v.y; s.z += v.z; s.w += v.w;
    }
    *(float4*)&g_hcat[i] = s;
}

// ---------------------------------------------------------------------------
// Kernel D: hidden_part[kb][b][j] = sum_{k in kb-range} hcat[b][k] * W1[k][j]
// 512 blocks (32 j-chunks x 16 k-chunks), 128 threads, acc[32] per thread.
// Scalar FFMA inner loop (f32x2 regressed in R4: RF bank limits + pack movs).
// launch_bounds(128,4): single wave (512/(148*4)=0.86), 16 warps/SM.
// ---------------------------------------------------------------------------
__global__ void __launch_bounds__(128, 4) k_gemm1(const float* __restrict__ W1) {
    int t = threadIdx.x;                  // 128
    int j = blockIdx.x * 128 + t;
    int k0 = blockIdx.y * 256;

    __shared__ float hs[128 * 36];        // 18 KB, rows 16B-aligned
    float acc[32];
#pragma unroll
    for (int i = 0; i < 32; i++) acc[i] = 0.f;

    for (int kt = 0; kt < 2; kt++) {
        int kb = k0 + kt * 128;
        __syncthreads();
        for (int i = t; i < 32 * 128; i += 128) {
            int b = i >> 7, kl = i & 127;
            hs[kl * 36 + b] = g_hcat[(size_t)b * FC + kb + kl];
        }
        __syncthreads();
        const float* wp = W1 + (size_t)kb * FC + j;
#pragma unroll 4
        for (int kl = 0; kl < 128; kl++) {
            float w = wp[(size_t)kl * FC];
            const float4* hp = (const float4*)&hs[kl * 36];
#pragma unroll
            for (int q4 = 0; q4 < 8; q4++) {
                float4 hv = hp[q4];
                acc[q4 * 4 + 0] = fmaf(hv.x, w, acc[q4 * 4 + 0]);
                acc[q4 * 4 + 1] = fmaf(hv.y, w, acc[q4 * 4 + 1]);
                acc[q4 * 4 + 2] = fmaf(hv.z, w, acc[q4 * 4 + 2]);
                acc[q4 * 4 + 3] = fmaf(hv.w, w, acc[q4 * 4 + 3]);
            }
        }
    }
    float* dst = g_hidden_part + (size_t)blockIdx.y * (Bz * FC) + j;
#pragma unroll
    for (int b = 0; b < 32; b++) dst[(size_t)b * FC] = acc[b];
}

// ---------------------------------------------------------------------------
// Kernel E: out[b][n] = b2[n] + sum_j relu(sum_kb hidden_part + b1[j]) * W2[j][n]
// ---------------------------------------------------------------------------
__global__ void k_out(const float* __restrict__ b1, const float* __restrict__ W2,
                      const float* __restrict__ b2, float* __restrict__ out) {
    int b = blockIdx.x;
    int t = threadIdx.x;   // 512
    float a0 = 0.f, a1 = 0.f, a2 = 0.f, a3 = 0.f;

    for (int j = t; j < FC; j += 512) {
        float hv = b1[j];
#pragma unroll
        for (int kb = 0; kb < 16; kb++)
            hv += g_hidden_part[((size_t)kb * Bz + b) * FC + j];
        hv = fmaxf(hv, 0.f);
        float4 w = *(const float4*)(W2 + (size_t)j * 4);
        a0 = fmaf(hv, w.x, a0);
        a1 = fmaf(hv, w.y, a1);
        a2 = fmaf(hv, w.z, a2);
        a3 = fmaf(hv, w.w, a3);
    }
#pragma unroll
    for (int off = 16; off; off >>= 1) {
        a0 += __shfl_xor_sync(0xffffffffu, a0, off);
        a1 += __shfl_xor_sync(0xffffffffu, a1, off);
        a2 += __shfl_xor_sync(0xffffffffu, a2, off);
        a3 += __shfl_xor_sync(0xffffffffu, a3, off);
    }
    __shared__ float s[16][4];
    if ((t & 31) == 0) {
        int w = t >> 5;
        s[w][0] = a0; s[w][1] = a1; s[w][2] = a2; s[w][3] = a3;
    }
    __syncthreads();
    if (t < 4) {
        float r = 0.f;
#pragma unroll
        for (int w = 0; w < 16; w++) r += s[w][t];
        out[b * 4 + t] = r + b2[t];
    }
}

// ---------------------------------------------------------------------------
extern "C" void kernel_launch(void* const* d_in, const int* in_sizes, int n_in,
                              void* d_out, int out_size) {
    const float* x  = (const float*)d_in[0];
    const int*   nf = (const int*)  d_in[1];
    const float* q  = (const float*)d_in[2];
    const float* W1 = (const float*)d_in[3];
    const float* b1 = (const float*)d_in[4];
    const float* W2 = (const float*)d_in[5];
    const float* b2 = (const float*)d_in[6];

    float* out_p  = (float*)d_out;              // (B, 4) = 128 floats
    float* attn_p = out_p + Bz * Oo;            // (O, F, B, H) = 1,048,576 floats

    const int smemA = (64 * 67 + 8 * 1056) * 4; // 50944 B > 48 KB default
    cudaFuncSetAttribute(k_logits, cudaFuncAttributeMaxDynamicSharedMemorySize, smemA);

    k_dummy<<<1, 1>>>();                        // shifts ncu capture slot to k_wsum

    dim3 gA(Bz, Ff / 8);
    k_logits<<<gA, 512, smemA>>>(x, nf, q);

    k_softmax<<<Oo * Bz, 256>>>(attn_p);

    dim3 gC(Bz, 8);
    k_wsum<<<gC, 1024>>>(x, nf, attn_p);

    k_csum<<<(Bz * FC) / (256 * 4), 256>>>();

    dim3 gD(FC / 128, 16);
    k_gemm1<<<gD, 128>>>(W1);

    k_out<<<Bz, 512>>>(b1, W2, b2, out_p);
}

// round 6
// speedup vs baseline: 1.2375x; 1.0012x over previous
#include <cuda_runtime.h>
#include <cstdint>
#include <cstddef>

#define Bz 32
#define Dd 1024
#define Ff 512
#define Hh 16
#define Oo 4
#define FC 4096
#define CH 16           // wsum chunks
#define FL 32           // frames per chunk

// Deterministic scratch (no device allocation allowed)
__device__ float g_logits[Oo * Bz * Hh * Ff];        // [o][b][h][f]  4 MB
__device__ float g_hcat_part[CH * Bz * FC];          // [chunk][b][o*1024+d] 8 MB
__device__ float g_hidden_part[16 * Bz * FC];        // [kblk][b][j]

// ---------------------------------------------------------------------------
// Kernel A: logits[o,b,h,f] = (x[f,b,h,:] . q[o,h,:]) / 8, masked to -50
// ---------------------------------------------------------------------------
__global__ void k_logits(const float* __restrict__ x, const int* __restrict__ nfp,
                         const float* __restrict__ q) {
    extern __shared__ float sm[];
    float* qs = sm;                 // 64 * 67
    float* xs = sm + 64 * 67;       // 8 * (16*66) = 8 * 1056
    int b  = blockIdx.x;
    int f0 = blockIdx.y * 8;
    int t  = threadIdx.x;
    int nf = nfp[b];

    for (int i = t; i < 64 * 64; i += 512)
        qs[(i >> 6) * 67 + (i & 63)] = q[i];

    for (int i = t; i < 8 * 512; i += 512) {
        int ff = i >> 9, j2 = i & 511;
        if (f0 + ff < nf) {
            int j = j2 * 2;
            float2 v = *(const float2*)&x[((size_t)(f0 + ff) * Bz + b) * Dd + j];
            *(float2*)&xs[ff * 1056 + (j >> 6) * 66 + (j & 63)] = v;
        }
    }
    __syncthreads();

    int fl = t >> 6;
    int oh = t & 63;
    int o = oh >> 4, h = oh & 15;
    int f = f0 + fl;

    float acc;
    if (f >= nf) {
        acc = -50.0f;
    } else {
        const float* xp = xs + fl * 1056 + h * 66;
        const float* qp = qs + oh * 67;
        float a = 0.f;
#pragma unroll
        for (int s = 0; s < 64; s++) a = fmaf(xp[s], qp[s], a);
        acc = a * 0.125f;
    }
    g_logits[((size_t)(o * Bz + b) * Hh + h) * Ff + f] = acc;
}

// ---------------------------------------------------------------------------
// Kernel B: softmax over f, writes attn in reference layout [o][f][b][h].
// ---------------------------------------------------------------------------
__global__ void k_softmax(float* __restrict__ attn) {
    int ob = blockIdx.x;
    int o = ob >> 5, b = ob & 31;
    int t = threadIdx.x;           // 256
    int w = t >> 5, lane = t & 31;

    __shared__ float ls[Hh * Ff];  // 32 KB
    __shared__ float si[Hh];

    const float* src = g_logits + (size_t)(o * Bz + b) * Hh * Ff;
    for (int i = t; i < Hh * Ff; i += 256) ls[i] = src[i];
    __syncthreads();

    for (int hh = w; hh < Hh; hh += 8) {
        float* lp = ls + hh * Ff;
        float m = -1e30f;
        for (int k = lane; k < Ff; k += 32) m = fmaxf(m, lp[k]);
#pragma unroll
        for (int off = 16; off; off >>= 1)
            m = fmaxf(m, __shfl_xor_sync(0xffffffffu, m, off));
        float s = 0.f;
        for (int k = lane; k < Ff; k += 32) {
            float e = __expf(lp[k] - m);
            lp[k] = e;
            s += e;
        }
#pragma unroll
        for (int off = 16; off; off >>= 1)
            s += __shfl_xor_sync(0xffffffffu, s, off);
        if (lane == 0) si[hh] = 1.0f / s;
    }
    __syncthreads();

    float* dst = attn + (size_t)o * Ff * Bz * Hh + b * Hh;
    for (int i = t; i < Hh * Ff; i += 256) {
        int f = i >> 4, hh = i & 15;
        dst[(size_t)f * (Bz * Hh) + hh] = ls[hh * Ff + f] * si[hh];
    }
}

// ---------------------------------------------------------------------------
// Kernel C: partial weighted sums, 16 chunks x 32 frames (MLP 8 via unroll).
// ---------------------------------------------------------------------------
__global__ void k_wsum(const float* __restrict__ x, const int* __restrict__ nfp,
                       const float* __restrict__ attn) {
    int b = blockIdx.x;
    int c = blockIdx.y;
    int f0 = c * FL;
    int nf = nfp[b];
    int d = threadIdx.x;
    int h = d >> 6;

    __shared__ float as[Oo * FL * Hh];   // [o][fl][h] 8 KB
    float a0 = 0.f, a1 = 0.f, a2 = 0.f, a3 = 0.f;

    if (f0 < nf) {
        for (int i = d; i < Oo * FL * Hh; i += 1024) {
            int o = i >> 9, r = i & 511;   // r = fl*16 + h
            as[i] = attn[(size_t)o * (Ff * Bz * Hh) +
                         (size_t)(f0 + (r >> 4)) * (Bz * Hh) + b * Hh + (r & 15)];
        }
        __syncthreads();
        int fe = min(FL, nf - f0);
        const float* xp = x + ((size_t)f0 * Bz + b) * Dd + d;
        if (fe == FL) {
#pragma unroll 8
            for (int fl = 0; fl < FL; fl++) {
                float xv = xp[(size_t)fl * (Bz * Dd)];
                int ai = fl * 16 + h;
                a0 = fmaf(xv, as[ai],       a0);
                a1 = fmaf(xv, as[512 + ai], a1);
                a2 = fmaf(xv, as[1024 + ai], a2);
                a3 = fmaf(xv, as[1536 + ai], a3);
            }
        } else {
            for (int fl = 0; fl < fe; fl++) {
                float xv = xp[(size_t)fl * (Bz * Dd)];
                int ai = fl * 16 + h;
                a0 = fmaf(xv, as[ai],       a0);
                a1 = fmaf(xv, as[512 + ai], a1);
                a2 = fmaf(xv, as[1024 + ai], a2);
                a3 = fmaf(xv, as[1536 + ai], a3);
            }
        }
    }
    float* p = g_hcat_part + ((size_t)c * Bz + b) * FC + d;
    p[0] = a0; p[1024] = a1; p[2048] = a2; p[3072] = a3;
}

// ---------------------------------------------------------------------------
// Kernel D: hidden_part[kb][b][j] = sum_k hcat[b][k] * W1[k][j]
// Chunk-partial summation folded into smem staging (hides under FFMA floor;
// g_hcat_part is L2-resident). Scalar FFMA inner loop, 32 accumulators.
// ---------------------------------------------------------------------------
__global__ void __launch_bounds__(128, 4) k_gemm1(const float* __restrict__ W1) {
    int t = threadIdx.x;                  // 128
    int j = blockIdx.x * 128 + t;
    int k0 = blockIdx.y * 256;

    __shared__ float hs[128 * 36];        // 18 KB, rows 16B-aligned
    float acc[32];
#pragma unroll
    for (int i = 0; i < 32; i++) acc[i] = 0.f;

    for (int kt = 0; kt < 2; kt++) {
        int kb = k0 + kt * 128;
        __syncthreads();
        for (int i = t; i < 32 * 128; i += 128) {
            int b = i >> 7, kl = i & 127;
            const float* pp = g_hcat_part + (size_t)b * FC + kb + kl;
            float s = 0.f;
#pragma unroll
            for (int c = 0; c < CH; c++) s += pp[(size_t)c * (Bz * FC)];
            hs[kl * 36 + b] = s;
        }
        __syncthreads();
        const float* wp = W1 + (size_t)kb * FC + j;
#pragma unroll 4
        for (int kl = 0; kl < 128; kl++) {
            float w = wp[(size_t)kl * FC];
            const float4* hp = (const float4*)&hs[kl * 36];
#pragma unroll
            for (int q4 = 0; q4 < 8; q4++) {
                float4 hv = hp[q4];
                acc[q4 * 4 + 0] = fmaf(hv.x, w, acc[q4 * 4 + 0]);
                acc[q4 * 4 + 1] = fmaf(hv.y, w, acc[q4 * 4 + 1]);
                acc[q4 * 4 + 2] = fmaf(hv.z, w, acc[q4 * 4 + 2]);
                acc[q4 * 4 + 3] = fmaf(hv.w, w, acc[q4 * 4 + 3]);
            }
        }
    }
    float* dst = g_hidden_part + (size_t)blockIdx.y * (Bz * FC) + j;
#pragma unroll
    for (int b = 0; b < 32; b++) dst[(size_t)b * FC] = acc[b];
}

// ---------------------------------------------------------------------------
// Kernel E: out[b][n] = b2[n] + sum_j relu(sum_kb hidden_part + b1[j]) * W2[j][n]
// float4 over j: 16 independent LDG.128 per j4 -> high MLP.
// ---------------------------------------------------------------------------
__global__ void k_out(const float* __restrict__ b1, const float* __restrict__ W2,
                      const float* __restrict__ b2, float* __restrict__ out) {
    int b = blockIdx.x;
    int t = threadIdx.x;   // 256
    float a0 = 0.f, a1 = 0.f, a2 = 0.f, a3 = 0.f;

#pragma unroll
    for (int p = 0; p < 4; p++) {
        int j = (t + p * 256) * 4;
        float4 hv = *(const float4*)(b1 + j);
#pragma unroll
        for (int kb = 0; kb < 16; kb++) {
            float4 v = *(const float4*)&g_hidden_part[((size_t)kb * Bz + b) * FC + j];
            hv.x += v.x; hv.y += v.y; hv.z += v.z; hv.w += v.w;
        }
        hv.x = fmaxf(hv.x, 0.f); hv.y = fmaxf(hv.y, 0.f);
        hv.z = fmaxf(hv.z, 0.f); hv.w = fmaxf(hv.w, 0.f);
#pragma unroll
        for (int e = 0; e < 4; e++) {
            float h = e == 0 ? hv.x : e == 1 ? hv.y : e == 2 ? hv.z : hv.w;
            float4 w = *(const float4*)(W2 + (size_t)(j + e) * 4);
            a0 = fmaf(h, w.x, a0);
            a1 = fmaf(h, w.y, a1);
            a2 = fmaf(h, w.z, a2);
            a3 = fmaf(h, w.w, a3);
        }
    }
#pragma unroll
    for (int off = 16; off; off >>= 1) {
        a0 += __shfl_xor_sync(0xffffffffu, a0, off);
        a1 += __shfl_xor_sync(0xffffffffu, a1, off);
        a2 += __shfl_xor_sync(0xffffffffu, a2, off);
        a3 += __shfl_xor_sync(0xffffffffu, a3, off);
    }
    __shared__ float s[8][4];
    if ((t & 31) == 0) {
        int w = t >> 5;
        s[w][0] = a0; s[w][1] = a1; s[w][2] = a2; s[w][3] = a3;
    }
    __syncthreads();
    if (t < 4) {
        float r = 0.f;
#pragma unroll
        for (int w = 0; w < 8; w++) r += s[w][t];
        out[b * 4 + t] = r + b2[t];
    }
}

// ---------------------------------------------------------------------------
extern "C" void kernel_launch(void* const* d_in, const int* in_sizes, int n_in,
                              void* d_out, int out_size) {
    const float* x  = (const float*)d_in[0];
    const int*   nf = (const int*)  d_in[1];
    const float* q  = (const float*)d_in[2];
    const float* W1 = (const float*)d_in[3];
    const float* b1 = (const float*)d_in[4];
    const float* W2 = (const float*)d_in[5];
    const float* b2 = (const float*)d_in[6];

    float* out_p  = (float*)d_out;              // (B, 4) = 128 floats
    float* attn_p = out_p + Bz * Oo;            // (O, F, B, H) = 1,048,576 floats

    const int smemA = (64 * 67 + 8 * 1056) * 4; // 50944 B > 48 KB default
    cudaFuncSetAttribute(k_logits, cudaFuncAttributeMaxDynamicSharedMemorySize, smemA);

    dim3 gA(Bz, Ff / 8);
    k_logits<<<gA, 512, smemA>>>(x, nf, q);

    k_softmax<<<Oo * Bz, 256>>>(attn_p);

    dim3 gC(Bz, CH);
    k_wsum<<<gC, 1024>>>(x, nf, attn_p);

    dim3 gD(FC / 128, 16);
    k_gemm1<<<gD, 128>>>(W1);                   // 4th launch -> ncu capture slot

    k_out<<<Bz, 256>>>(b1, W2, b2, out_p);
}